// round 5
// baseline (speedup 1.0000x reference)
#include <cuda_runtime.h>
#include <cstdint>

#define WPB 8          // warps per block
#define EPW 8          // elements per warp
#define NTHREADS 256
#define D 64
#define NS 8

typedef unsigned long long ull;

__device__ __forceinline__ ull pack2(float x, float y){
    ull r;
    asm("mov.b64 %0, {%1, %2};" : "=l"(r)
        : "r"(__float_as_uint(x)), "r"(__float_as_uint(y)));
    return r;
}
__device__ __forceinline__ void unpack2(ull p, float &x, float &y){
    unsigned int lo, hi;
    asm("mov.b64 {%0, %1}, %2;" : "=r"(lo), "=r"(hi) : "l"(p));
    x = __uint_as_float(lo); y = __uint_as_float(hi);
}
// packed fp32x2 ops (Blackwell)
__device__ __forceinline__ void ffma2(ull &acc, ull a, ull b){
    asm("fma.rn.f32x2 %0, %1, %2, %3;" : "=l"(acc) : "l"(a), "l"(b), "l"(acc));
}
__device__ __forceinline__ ull add2(ull a, ull b){
    ull r; asm("add.rn.f32x2 %0, %1, %2;" : "=l"(r) : "l"(a), "l"(b));
    return r;
}

// softmax over 8-lane group (lanes 8g..8g+7), one value per lane
__device__ __forceinline__ float gsoftmax8(float x){
    float m = x;
    m = fmaxf(m, __shfl_xor_sync(0xffffffffu, m, 1));
    m = fmaxf(m, __shfl_xor_sync(0xffffffffu, m, 2));
    m = fmaxf(m, __shfl_xor_sync(0xffffffffu, m, 4));
    float e = __expf(x - m);
    float sm = e;
    sm += __shfl_xor_sync(0xffffffffu, sm, 1);
    sm += __shfl_xor_sync(0xffffffffu, sm, 2);
    sm += __shfl_xor_sync(0xffffffffu, sm, 4);
    return e / sm;
}

// matvec: W from gmem (L1-resident), x from smem as duplicated pairs via LDS.128.
// sxw points at this warp's [EPW][2*D] float region. Output pair per lane, relu'd.
__device__ __forceinline__ void matvec(const ull* __restrict__ Wg,
                                       const ull* __restrict__ bg,
                                       const float* __restrict__ sxw,
                                       ull* h, int lane){
    ull bias = bg[lane];
    ull acc[EPW];
    #pragma unroll
    for (int e = 0; e < EPW; e++) acc[e] = bias;
    #pragma unroll 8
    for (int dd = 0; dd < D/2; dd++){
        ull w0 = Wg[(2*dd)  * 32 + lane];   // (W[2dd][2l],   W[2dd][2l+1])
        ull w1 = Wg[(2*dd+1)* 32 + lane];
        #pragma unroll
        for (int e = 0; e < EPW; e++){
            ulonglong2 xp = *(const ulonglong2*)(sxw + e*(2*D) + 4*dd);
            ffma2(acc[e], w0, xp.x);        // (x[2dd],   x[2dd])
            ffma2(acc[e], w1, xp.y);        // (x[2dd+1], x[2dd+1])
        }
    }
    #pragma unroll
    for (int e = 0; e < EPW; e++){
        float a, b; unpack2(acc[e], a, b);
        h[e] = pack2(fmaxf(a, 0.f), fmaxf(b, 0.f));
    }
}

__global__ void __launch_bounds__(NTHREADS, 4)
sestkgcn_kernel(
    const int* __restrict__ u, const int* __restrict__ v,
    const float* __restrict__ usr_feat, const float* __restrict__ item_feat,
    const float* __restrict__ rel_feat,
    const int* __restrict__ neigh_uu, const float* __restrict__ uu_st,
    const int* __restrict__ neigh_ui, const float* __restrict__ ui_rat,
    const float* __restrict__ ui_vot, const float* __restrict__ ui_tim,
    const int* __restrict__ neigh_iu, const float* __restrict__ iu_rat,
    const float* __restrict__ iu_vot, const float* __restrict__ iu_tim,
    const int* __restrict__ neigh_ii, const int* __restrict__ neigh_ir,
    const float* __restrict__ Wu, const float* __restrict__ bu,
    const float* __restrict__ Wv, const float* __restrict__ bv,
    float* __restrict__ out, int batch)
{
    // duplicated-pair x vectors: 8 warps * 8 elems * 128 floats = 32 KB
    __shared__ __align__(16) float sx[WPB][EPW][2*D];
    // lane-parallel (weight,index) packs: 8 warps * 4 hops * 64 slots = 16 KB
    __shared__ ull pbuf[WPB][4][EPW*NS];

    const int lane = threadIdx.x & 31;
    const int warp = threadIdx.x >> 5;
    const int base = (blockIdx.x * WPB + warp) * EPW;

    const float2* usr2  = (const float2*)usr_feat;   // pair base = id*32 + lane
    const float2* item2 = (const float2*)item_feat;
    const float4* usr4  = (const float4*)usr_feat;   // chunk base = id*16 + t
    const float4* rel4  = (const float4*)rel_feat;

    const int eg = lane >> 3, sg = lane & 7;         // lane = (element-in-round, neighbor)

    int myu2[2], myv2[2];

    // ---------- per-round (4 elements each) lane-parallel weights, indices, KG attention ----------
    #pragma unroll
    for (int r = 0; r < 2; r++){
        int bb = base + 4*r + eg; if (bb >= batch) bb = batch - 1;
        const int myu = u[bb];
        const int myv = v[bb];
        myu2[r] = myu; myv2[r] = myv;

        float wuu = uu_st[myu*NS + sg];
        int   iuu = neigh_uu[myu*NS + sg];
        float wui = ui_rat[myu*NS + sg] * ui_vot[myu*NS + sg] * ui_tim[myu*NS + sg];
        int   iui = neigh_ui[myu*NS + sg];
        float wiu = iu_rat[myv*NS + sg] * iu_vot[myv*NS + sg] * iu_tim[myv*NS + sg];
        int   iiu = neigh_iu[myv*NS + sg];
        int   iii = neigh_ii[myv*NS + sg];
        int   iir = neigh_ir[myv*NS + sg];

        wuu = gsoftmax8(wuu);
        wui = gsoftmax8(wui);
        wiu = gsoftmax8(wiu);

        // KG attention score: each lane privately computes dot(u_emb[myu], rel[iir])
        const float4* ur = usr4 + (size_t)myu*16;
        const float4* rr = rel4 + (size_t)iir*16;
        float dt = 0.f;
        #pragma unroll
        for (int t = 0; t < 16; t++){
            float4 a = ur[t], b = rr[t];
            dt = fmaf(a.x, b.x, dt);
            dt = fmaf(a.y, b.y, dt);
            dt = fmaf(a.z, b.z, dt);
            dt = fmaf(a.w, b.w, dt);
        }
        float watt = gsoftmax8(dt);

        const int slot = (4*r + eg)*NS + sg;
        pbuf[warp][0][slot] = pack2(wuu,  __int_as_float(iuu));
        pbuf[warp][1][slot] = pack2(wui,  __int_as_float(iui));
        pbuf[warp][2][slot] = pack2(wiu,  __int_as_float(iiu));
        pbuf[warp][3][slot] = pack2(watt, __int_as_float(iii));
    }
    __syncwarp();

    // =============== user side: gather + aggregate ===============
    #pragma unroll
    for (int r = 0; r < 2; r++){
        #pragma unroll 2
        for (int e2 = 0; e2 < 4; e2++){
            const int e = 4*r + e2;
            int uid = __shfl_sync(0xffffffffu, myu2[r], e2 << 3);
            float2 t0 = usr2[(size_t)uid*32 + lane];
            float ax = t0.x, ay = t0.y;

            // social neighbors
            {
                float w[NS]; int idx[NS];
                #pragma unroll
                for (int s = 0; s < NS; s++){
                    float wf, idf; unpack2(pbuf[warp][0][e*NS + s], wf, idf);
                    w[s] = wf; idx[s] = __float_as_int(idf);
                }
                float2 f[NS];
                #pragma unroll
                for (int s = 0; s < NS; s++) f[s] = usr2[(size_t)idx[s]*32 + lane];
                #pragma unroll
                for (int s = 0; s < NS; s++){
                    ax = fmaf(w[s], f[s].x, ax);
                    ay = fmaf(w[s], f[s].y, ay);
                }
            }
            // interacted items
            {
                float w[NS]; int idx[NS];
                #pragma unroll
                for (int s = 0; s < NS; s++){
                    float wf, idf; unpack2(pbuf[warp][1][e*NS + s], wf, idf);
                    w[s] = wf; idx[s] = __float_as_int(idf);
                }
                float2 f[NS];
                #pragma unroll
                for (int s = 0; s < NS; s++) f[s] = item2[(size_t)idx[s]*32 + lane];
                #pragma unroll
                for (int s = 0; s < NS; s++){
                    ax = fmaf(w[s], f[s].x, ax);
                    ay = fmaf(w[s], f[s].y, ay);
                }
            }
            *(float4*)(&sx[warp][e][4*lane]) = make_float4(ax, ax, ay, ay);
        }
    }
    __syncwarp();

    // =============== user matvec: relu(x @ Wu + bu) ===============
    ull uh[EPW];
    matvec((const ull*)Wu, (const ull*)bu, &sx[warp][0][0], uh, lane);
    __syncwarp();   // matvec reads done before item phase overwrites sx

    // =============== item side: gather + aggregate ===============
    #pragma unroll
    for (int r = 0; r < 2; r++){
        #pragma unroll 2
        for (int e2 = 0; e2 < 4; e2++){
            const int e = 4*r + e2;
            int vid = __shfl_sync(0xffffffffu, myv2[r], e2 << 3);
            float2 t0 = item2[(size_t)vid*32 + lane];
            float ax = t0.x, ay = t0.y;

            // interacting users
            {
                float w[NS]; int idx[NS];
                #pragma unroll
                for (int s = 0; s < NS; s++){
                    float wf, idf; unpack2(pbuf[warp][2][e*NS + s], wf, idf);
                    w[s] = wf; idx[s] = __float_as_int(idf);
                }
                float2 f[NS];
                #pragma unroll
                for (int s = 0; s < NS; s++) f[s] = usr2[(size_t)idx[s]*32 + lane];
                #pragma unroll
                for (int s = 0; s < NS; s++){
                    ax = fmaf(w[s], f[s].x, ax);
                    ay = fmaf(w[s], f[s].y, ay);
                }
            }
            // KG neighbors (attention weights precomputed)
            {
                float w[NS]; int idx[NS];
                #pragma unroll
                for (int s = 0; s < NS; s++){
                    float wf, idf; unpack2(pbuf[warp][3][e*NS + s], wf, idf);
                    w[s] = wf; idx[s] = __float_as_int(idf);
                }
                float2 f[NS];
                #pragma unroll
                for (int s = 0; s < NS; s++) f[s] = item2[(size_t)idx[s]*32 + lane];
                #pragma unroll
                for (int s = 0; s < NS; s++){
                    ax = fmaf(w[s], f[s].x, ax);
                    ay = fmaf(w[s], f[s].y, ay);
                }
            }
            *(float4*)(&sx[warp][e][4*lane]) = make_float4(ax, ax, ay, ay);
        }
    }
    __syncwarp();

    // =============== item matvec: relu(x @ Wv + bv) ===============
    ull vh[EPW];
    matvec((const ull*)Wv, (const ull*)bv, &sx[warp][0][0], vh, lane);

    // =============== score: sigmoid(dot(user_h, item_h)) * 5 ===============
    float pe[EPW];
    #pragma unroll
    for (int e = 0; e < EPW; e++){
        float a0, a1, b0, b1;
        unpack2(uh[e], a0, a1);
        unpack2(vh[e], b0, b1);
        pe[e] = fmaf(a0, b0, a1 * b1);
    }
    ull s0 = pack2(pe[0], pe[1]), s1 = pack2(pe[2], pe[3]);
    ull s2 = pack2(pe[4], pe[5]), s3 = pack2(pe[6], pe[7]);
    #pragma unroll
    for (int o = 16; o; o >>= 1){
        s0 = add2(s0, __shfl_xor_sync(0xffffffffu, s0, o));
        s1 = add2(s1, __shfl_xor_sync(0xffffffffu, s1, o));
        s2 = add2(s2, __shfl_xor_sync(0xffffffffu, s2, o));
        s3 = add2(s3, __shfl_xor_sync(0xffffffffu, s3, o));
    }
    if (lane == 0){
        float r[EPW];
        unpack2(s0, r[0], r[1]); unpack2(s1, r[2], r[3]);
        unpack2(s2, r[4], r[5]); unpack2(s3, r[6], r[7]);
        #pragma unroll
        for (int e = 0; e < EPW; e++) r[e] = 5.f / (1.f + __expf(-r[e]));
        if (base + EPW <= batch){
            float4* o4 = (float4*)(out + base);
            o4[0] = make_float4(r[0], r[1], r[2], r[3]);
            o4[1] = make_float4(r[4], r[5], r[6], r[7]);
        } else {
            for (int e = 0; e < EPW; e++)
                if (base + e < batch) out[base + e] = r[e];
        }
    }
}

extern "C" void kernel_launch(void* const* d_in, const int* in_sizes, int n_in,
                              void* d_out, int out_size)
{
    (void)n_in; (void)out_size;
    const int batch = in_sizes[0];
    const int blocks = (batch + WPB*EPW - 1) / (WPB*EPW);
    sestkgcn_kernel<<<blocks, NTHREADS>>>(
        (const int*)d_in[0],  (const int*)d_in[1],
        (const float*)d_in[2], (const float*)d_in[3], (const float*)d_in[4],
        (const int*)d_in[5],  (const float*)d_in[6],
        (const int*)d_in[7],  (const float*)d_in[8],  (const float*)d_in[9],  (const float*)d_in[10],
        (const int*)d_in[11], (const float*)d_in[12], (const float*)d_in[13], (const float*)d_in[14],
        (const int*)d_in[15], (const int*)d_in[16],
        (const float*)d_in[17], (const float*)d_in[18],
        (const float*)d_in[19], (const float*)d_in[20],
        (float*)d_out, batch);
}

// round 6
// speedup vs baseline: 1.1176x; 1.1176x over previous
#include <cuda_runtime.h>
#include <cstdint>

#define WPB 8          // warps per block
#define EPW 8          // elements per warp
#define NTHREADS 256
#define D 64
#define NS 8

typedef unsigned long long ull;

__device__ __forceinline__ ull pack2(float x, float y){
    ull r;
    asm("mov.b64 %0, {%1, %2};" : "=l"(r)
        : "r"(__float_as_uint(x)), "r"(__float_as_uint(y)));
    return r;
}
__device__ __forceinline__ void unpack2(ull p, float &x, float &y){
    unsigned int lo, hi;
    asm("mov.b64 {%0, %1}, %2;" : "=r"(lo), "=r"(hi) : "l"(p));
    x = __uint_as_float(lo); y = __uint_as_float(hi);
}
// packed fp32x2 ops (Blackwell)
__device__ __forceinline__ void ffma2(ull &acc, ull a, ull b){
    asm("fma.rn.f32x2 %0, %1, %2, %3;" : "=l"(acc) : "l"(a), "l"(b), "l"(acc));
}
__device__ __forceinline__ ull add2(ull a, ull b){
    ull r; asm("add.rn.f32x2 %0, %1, %2;" : "=l"(r) : "l"(a), "l"(b));
    return r;
}

// softmax over 8-lane group (lanes 8g..8g+7), one value per lane
__device__ __forceinline__ float gsoftmax8(float x){
    float m = x;
    m = fmaxf(m, __shfl_xor_sync(0xffffffffu, m, 1));
    m = fmaxf(m, __shfl_xor_sync(0xffffffffu, m, 2));
    m = fmaxf(m, __shfl_xor_sync(0xffffffffu, m, 4));
    float e = __expf(x - m);
    float sm = e;
    sm += __shfl_xor_sync(0xffffffffu, sm, 1);
    sm += __shfl_xor_sync(0xffffffffu, sm, 2);
    sm += __shfl_xor_sync(0xffffffffu, sm, 4);
    return e / sm;
}

// replicated 8-way softmax (values already held by every lane)
__device__ __forceinline__ void softmax8(float* w){
    float m = w[0];
    #pragma unroll
    for (int s = 1; s < NS; s++) m = fmaxf(m, w[s]);
    float sum = 0.f;
    #pragma unroll
    for (int s = 0; s < NS; s++){ w[s] = __expf(w[s] - m); sum += w[s]; }
    float inv = 1.f / sum;
    #pragma unroll
    for (int s = 0; s < NS; s++) w[s] *= inv;
}

// read 8 (weight,index) packs for (hop,e) via 4 LDS.128 broadcasts
__device__ __forceinline__ void read_packs(const ull* p, float* w, int* idx){
    #pragma unroll
    for (int q = 0; q < 4; q++){
        ulonglong2 t = *(const ulonglong2*)(p + 2*q);
        float a, b;
        unpack2(t.x, a, b); w[2*q]   = a; idx[2*q]   = __float_as_int(b);
        unpack2(t.y, a, b); w[2*q+1] = a; idx[2*q+1] = __float_as_int(b);
    }
}

// matvec: W from gmem (L1-resident), x from smem as duplicated pairs via LDS.128.
// sxw points at this warp's [EPW][2*D] float region. Output pair per lane, relu'd.
__device__ __forceinline__ void matvec(const ull* __restrict__ Wg,
                                       const ull* __restrict__ bg,
                                       const float* __restrict__ sxw,
                                       ull* h, int lane){
    ull bias = bg[lane];
    ull acc[EPW];
    #pragma unroll
    for (int e = 0; e < EPW; e++) acc[e] = bias;
    #pragma unroll 4
    for (int dd = 0; dd < D/2; dd++){
        ull w0 = Wg[(2*dd)  * 32 + lane];   // (W[2dd][2l],   W[2dd][2l+1])
        ull w1 = Wg[(2*dd+1)* 32 + lane];
        #pragma unroll
        for (int e = 0; e < EPW; e++){
            ulonglong2 xp = *(const ulonglong2*)(sxw + e*(2*D) + 4*dd);
            ffma2(acc[e], w0, xp.x);        // (x[2dd],   x[2dd])
            ffma2(acc[e], w1, xp.y);        // (x[2dd+1], x[2dd+1])
        }
    }
    #pragma unroll
    for (int e = 0; e < EPW; e++){
        float a, b; unpack2(acc[e], a, b);
        h[e] = pack2(fmaxf(a, 0.f), fmaxf(b, 0.f));
    }
}

__global__ void __launch_bounds__(NTHREADS, 4)
sestkgcn_kernel(
    const int* __restrict__ u, const int* __restrict__ v,
    const float* __restrict__ usr_feat, const float* __restrict__ item_feat,
    const float* __restrict__ rel_feat,
    const int* __restrict__ neigh_uu, const float* __restrict__ uu_st,
    const int* __restrict__ neigh_ui, const float* __restrict__ ui_rat,
    const float* __restrict__ ui_vot, const float* __restrict__ ui_tim,
    const int* __restrict__ neigh_iu, const float* __restrict__ iu_rat,
    const float* __restrict__ iu_vot, const float* __restrict__ iu_tim,
    const int* __restrict__ neigh_ii, const int* __restrict__ neigh_ir,
    const float* __restrict__ Wu, const float* __restrict__ bu,
    const float* __restrict__ Wv, const float* __restrict__ bv,
    float* __restrict__ out, int batch)
{
    // duplicated-pair x vectors: 8 warps * 8 elems * 128 floats = 32 KB
    __shared__ __align__(16) float sx[WPB][EPW][2*D];
    // lane-parallel (weight,index) packs: 8 warps * 4 hops * 64 slots = 16 KB
    __shared__ __align__(16) ull pbuf[WPB][4][EPW*NS];

    const int lane = threadIdx.x & 31;
    const int warp = threadIdx.x >> 5;
    const int base = (blockIdx.x * WPB + warp) * EPW;

    const float2* usr2  = (const float2*)usr_feat;   // pair base = id*32 + lane
    const float2* item2 = (const float2*)item_feat;
    const float2* rel2  = (const float2*)rel_feat;

    const int eg = lane >> 3, sg = lane & 7;         // lane = (element-in-round, neighbor)

    int myu2[2], myv2[2];

    // ---------- lane-parallel weights & indices (2 rounds of 4 elements) ----------
    #pragma unroll
    for (int r = 0; r < 2; r++){
        int bb = base + 4*r + eg; if (bb >= batch) bb = batch - 1;
        const int myu = u[bb];
        const int myv = v[bb];
        myu2[r] = myu; myv2[r] = myv;

        float wuu = uu_st[myu*NS + sg];
        int   iuu = neigh_uu[myu*NS + sg];
        float wui = ui_rat[myu*NS + sg] * ui_vot[myu*NS + sg] * ui_tim[myu*NS + sg];
        int   iui = neigh_ui[myu*NS + sg];
        float wiu = iu_rat[myv*NS + sg] * iu_vot[myv*NS + sg] * iu_tim[myv*NS + sg];
        int   iiu = neigh_iu[myv*NS + sg];
        int   iii = neigh_ii[myv*NS + sg];
        int   iir = neigh_ir[myv*NS + sg];

        wuu = gsoftmax8(wuu);
        wui = gsoftmax8(wui);
        wiu = gsoftmax8(wiu);

        const int slot = (4*r + eg)*NS + sg;
        pbuf[warp][0][slot] = pack2(wuu, __int_as_float(iuu));
        pbuf[warp][1][slot] = pack2(wui, __int_as_float(iui));
        pbuf[warp][2][slot] = pack2(wiu, __int_as_float(iiu));
        pbuf[warp][3][slot] = pack2(__int_as_float(iii), __int_as_float(iir));
    }
    __syncwarp();

    // =============== user side: gather + aggregate ===============
    #pragma unroll 2
    for (int e = 0; e < EPW; e++){
        int uid = __shfl_sync(0xffffffffu, myu2[e >> 2], (e & 3) << 3);
        float2 t0 = usr2[(size_t)uid*32 + lane];
        float ax = t0.x, ay = t0.y;

        // social neighbors
        {
            float w[NS]; int idx[NS]; float2 f[NS];
            read_packs(&pbuf[warp][0][e*NS], w, idx);
            #pragma unroll
            for (int s = 0; s < NS; s++) f[s] = usr2[(size_t)idx[s]*32 + lane];
            #pragma unroll
            for (int s = 0; s < NS; s++){
                ax = fmaf(w[s], f[s].x, ax);
                ay = fmaf(w[s], f[s].y, ay);
            }
        }
        // interacted items
        {
            float w[NS]; int idx[NS]; float2 f[NS];
            read_packs(&pbuf[warp][1][e*NS], w, idx);
            #pragma unroll
            for (int s = 0; s < NS; s++) f[s] = item2[(size_t)idx[s]*32 + lane];
            #pragma unroll
            for (int s = 0; s < NS; s++){
                ax = fmaf(w[s], f[s].x, ax);
                ay = fmaf(w[s], f[s].y, ay);
            }
        }
        *(float4*)(&sx[warp][e][4*lane]) = make_float4(ax, ax, ay, ay);
    }
    __syncwarp();

    // =============== user matvec: relu(x @ Wu + bu) ===============
    ull uh[EPW];
    matvec((const ull*)Wu, (const ull*)bu, &sx[warp][0][0], uh, lane);
    __syncwarp();   // matvec reads done before item phase overwrites sx

    // =============== item side: gather + aggregate ===============
    #pragma unroll 2
    for (int e = 0; e < EPW; e++){
        int vid = __shfl_sync(0xffffffffu, myv2[e >> 2], (e & 3) << 3);
        float2 t0 = item2[(size_t)vid*32 + lane];
        float ax = t0.x, ay = t0.y;

        // interacting users
        {
            float w[NS]; int idx[NS]; float2 f[NS];
            read_packs(&pbuf[warp][2][e*NS], w, idx);
            #pragma unroll
            for (int s = 0; s < NS; s++) f[s] = usr2[(size_t)idx[s]*32 + lane];
            #pragma unroll
            for (int s = 0; s < NS; s++){
                ax = fmaf(w[s], f[s].x, ax);
                ay = fmaf(w[s], f[s].y, ay);
            }
        }
        // KG neighbors with user-relation attention (warp-gathered rel + butterfly)
        {
            int uid = __shfl_sync(0xffffffffu, myu2[e >> 2], (e & 3) << 3);
            float2 ue = usr2[(size_t)uid*32 + lane];   // L1-hit re-gather

            int iidx[NS], ridx[NS];
            #pragma unroll
            for (int q = 0; q < 4; q++){
                ulonglong2 t = *(const ulonglong2*)(&pbuf[warp][3][e*NS + 2*q]);
                float a, b;
                unpack2(t.x, a, b); iidx[2*q]   = __float_as_int(a); ridx[2*q]   = __float_as_int(b);
                unpack2(t.y, a, b); iidx[2*q+1] = __float_as_int(a); ridx[2*q+1] = __float_as_int(b);
            }
            float ps[NS];
            #pragma unroll
            for (int s = 0; s < NS; s++){
                float2 rf = rel2[(size_t)ridx[s]*32 + lane];
                ps[s] = fmaf(ue.x, rf.x, ue.y * rf.y);
            }
            // packed butterfly: reduce 8 dots across the warp simultaneously
            ull q0 = pack2(ps[0], ps[1]), q1 = pack2(ps[2], ps[3]);
            ull q2 = pack2(ps[4], ps[5]), q3 = pack2(ps[6], ps[7]);
            #pragma unroll
            for (int o = 16; o; o >>= 1){
                q0 = add2(q0, __shfl_xor_sync(0xffffffffu, q0, o));
                q1 = add2(q1, __shfl_xor_sync(0xffffffffu, q1, o));
                q2 = add2(q2, __shfl_xor_sync(0xffffffffu, q2, o));
                q3 = add2(q3, __shfl_xor_sync(0xffffffffu, q3, o));
            }
            float att[NS];
            unpack2(q0, att[0], att[1]); unpack2(q1, att[2], att[3]);
            unpack2(q2, att[4], att[5]); unpack2(q3, att[6], att[7]);
            softmax8(att);
            float2 f[NS];
            #pragma unroll
            for (int s = 0; s < NS; s++) f[s] = item2[(size_t)iidx[s]*32 + lane];
            #pragma unroll
            for (int s = 0; s < NS; s++){
                ax = fmaf(att[s], f[s].x, ax);
                ay = fmaf(att[s], f[s].y, ay);
            }
        }
        *(float4*)(&sx[warp][e][4*lane]) = make_float4(ax, ax, ay, ay);
    }
    __syncwarp();

    // =============== item matvec: relu(x @ Wv + bv) ===============
    ull vh[EPW];
    matvec((const ull*)Wv, (const ull*)bv, &sx[warp][0][0], vh, lane);

    // =============== score: sigmoid(dot(user_h, item_h)) * 5 ===============
    float pe[EPW];
    #pragma unroll
    for (int e = 0; e < EPW; e++){
        float a0, a1, b0, b1;
        unpack2(uh[e], a0, a1);
        unpack2(vh[e], b0, b1);
        pe[e] = fmaf(a0, b0, a1 * b1);
    }
    ull s0 = pack2(pe[0], pe[1]), s1 = pack2(pe[2], pe[3]);
    ull s2 = pack2(pe[4], pe[5]), s3 = pack2(pe[6], pe[7]);
    #pragma unroll
    for (int o = 16; o; o >>= 1){
        s0 = add2(s0, __shfl_xor_sync(0xffffffffu, s0, o));
        s1 = add2(s1, __shfl_xor_sync(0xffffffffu, s1, o));
        s2 = add2(s2, __shfl_xor_sync(0xffffffffu, s2, o));
        s3 = add2(s3, __shfl_xor_sync(0xffffffffu, s3, o));
    }
    if (lane == 0){
        float r[EPW];
        unpack2(s0, r[0], r[1]); unpack2(s1, r[2], r[3]);
        unpack2(s2, r[4], r[5]); unpack2(s3, r[6], r[7]);
        #pragma unroll
        for (int e = 0; e < EPW; e++) r[e] = 5.f / (1.f + __expf(-r[e]));
        if (base + EPW <= batch){
            float4* o4 = (float4*)(out + base);
            o4[0] = make_float4(r[0], r[1], r[2], r[3]);
            o4[1] = make_float4(r[4], r[5], r[6], r[7]);
        } else {
            for (int e = 0; e < EPW; e++)
                if (base + e < batch) out[base + e] = r[e];
        }
    }
}

extern "C" void kernel_launch(void* const* d_in, const int* in_sizes, int n_in,
                              void* d_out, int out_size)
{
    (void)n_in; (void)out_size;
    const int batch = in_sizes[0];
    const int blocks = (batch + WPB*EPW - 1) / (WPB*EPW);
    sestkgcn_kernel<<<blocks, NTHREADS>>>(
        (const int*)d_in[0],  (const int*)d_in[1],
        (const float*)d_in[2], (const float*)d_in[3], (const float*)d_in[4],
        (const int*)d_in[5],  (const float*)d_in[6],
        (const int*)d_in[7],  (const float*)d_in[8],  (const float*)d_in[9],  (const float*)d_in[10],
        (const int*)d_in[11], (const float*)d_in[12], (const float*)d_in[13], (const float*)d_in[14],
        (const int*)d_in[15], (const int*)d_in[16],
        (const float*)d_in[17], (const float*)d_in[18],
        (const float*)d_in[19], (const float*)d_in[20],
        (float*)d_out, batch);
}